// round 15
// baseline (speedup 1.0000x reference)
#include <cuda_runtime.h>
#include <cstdint>
#include <cmath>

#define BB   256
#define TT   1024
#define OBS  64
#define NN   512
#define AA   8
#define BETA 0.9f
#define V_TH 1.0f

#define BT      16                 // batch rows per block
#define NT      64                 // neurons per block
#define NBG     (BB / BT)          // 16 batch groups
#define NNT     (NN / NT)          // 8 tile-blocks per group
#define NPART   (NNT * 2)          // 16 partial slots per row (tile x half)
#define GRID    (NBG * NNT)        // 128 blocks, all co-resident (1/SM)
#define THREADS 1024               // 32 warps: warp = (row, half)

struct __align__(128) GroupBar { unsigned count; unsigned flag; unsigned pad[30]; };

// Scratch: __device__ globals (runtime allocation is forbidden)
__device__ float    g_WT[NN * NN];               // W_T[j][i] = W_rec[i][j]
__device__ float    g_I[(size_t)BB * TT * NN];   // x @ W_in^T, precomputed
__device__ unsigned g_mask[2][BB][NN / 32];      // spike bitmasks, parity-buffered
__device__ float    g_part[2][BB][NPART][AA];    // output partials, parity-buffered
__device__ GroupBar g_bar[NBG];                  // per-group barrier lines

// ---------- fused prep + input GEMM ----------
// blockIdx.y < 8 : GEMM tile  g_I[r,i] = sum_k X[r,k]*Win[i,k]  (bitwise-load-bearing)
// blockIdx.y == 8: prep plane (W transpose, mask(0) zero, barrier reset)
__global__ void __launch_bounds__(256, 2) fused_prep_ingemm(const float* __restrict__ X,
                                                            const float* __restrict__ Win,
                                                            const float* __restrict__ Wrec)
{
    if (blockIdx.y == 8) {
        int idx = blockIdx.x * 256 + threadIdx.x;
        if (idx < NN * NN) {
            int i = idx >> 9, j = idx & (NN - 1);
            g_WT[j * NN + i] = Wrec[idx];
        }
        if (idx < BB * (NN / 32)) ((unsigned*)g_mask)[idx] = 0u;   // g_mask[0] zeroed
        if (idx < NBG) { g_bar[idx].count = 0u; g_bar[idx].flag = 0u; }
        return;
    }

    __shared__ float As[128][OBS];
    __shared__ float Bs[OBS][64];
    const int row0 = blockIdx.x * 128;
    const int col0 = blockIdx.y * 64;
    const int tid  = threadIdx.x;

    #pragma unroll
    for (int l = tid; l < 128 * 16; l += 256) {
        int r = l >> 4, kq = l & 15;
        float4 v = reinterpret_cast<const float4*>(X + (size_t)(row0 + r) * OBS)[kq];
        *reinterpret_cast<float4*>(&As[r][kq * 4]) = v;
    }
    #pragma unroll
    for (int l = tid; l < 64 * 16; l += 256) {
        int i = l & 63, kq = l >> 6;
        float4 v = reinterpret_cast<const float4*>(Win + (size_t)(col0 + i) * OBS)[kq];
        Bs[kq * 4 + 0][i] = v.x;
        Bs[kq * 4 + 1][i] = v.y;
        Bs[kq * 4 + 2][i] = v.z;
        Bs[kq * 4 + 3][i] = v.w;
    }
    __syncthreads();

    const int tx = tid & 15, ty = tid >> 4;
    float acc[8][4];
    #pragma unroll
    for (int u = 0; u < 8; u++)
        #pragma unroll
        for (int c = 0; c < 4; c++) acc[u][c] = 0.f;

    #pragma unroll 8
    for (int k = 0; k < OBS; k++) {
        float4 b4 = *reinterpret_cast<const float4*>(&Bs[k][tx * 4]);
        #pragma unroll
        for (int u = 0; u < 8; u++) {
            float a = As[ty * 8 + u][k];
            acc[u][0] = __fmaf_rn(a, b4.x, acc[u][0]);
            acc[u][1] = __fmaf_rn(a, b4.y, acc[u][1]);
            acc[u][2] = __fmaf_rn(a, b4.z, acc[u][2]);
            acc[u][3] = __fmaf_rn(a, b4.w, acc[u][3]);
        }
    }
    #pragma unroll
    for (int u = 0; u < 8; u++) {
        size_t r = (size_t)(row0 + ty * 8 + u);
        float4 st = make_float4(acc[u][0], acc[u][1], acc[u][2], acc[u][3]);
        *reinterpret_cast<float4*>(&g_I[r * NN + col0 + tx * 4]) = st;
    }
}

// ---------- per-group barrier: 8 blocks, own 128B line, monotone target ----------
__device__ __forceinline__ void group_barrier(GroupBar* bar, unsigned target)
{
    __syncthreads();
    if (threadIdx.x == 0) {
        unsigned prev, one = 1u;
        asm volatile("atom.release.gpu.add.u32 %0, [%1], %2;"
                     : "=r"(prev) : "l"(&bar->count), "r"(one) : "memory");
        if (prev == target * NNT - 1u) {
            asm volatile("st.release.gpu.u32 [%0], %1;"
                         :: "l"(&bar->flag), "r"(target) : "memory");
        } else {
            unsigned f;
            do {
                asm volatile("ld.acquire.gpu.u32 %0, [%1];"
                             : "=r"(f) : "l"(&bar->flag) : "memory");
            } while (f < target);
        }
    }
    __syncthreads();
}

// ---------- persistent LIF: W slice in SMEM, 2 warps per batch row ----------
// block = (batch group bg) x (neuron tile nt). warp = (row w2 = warp>>1,
// half h = warp&1); lane owns exactly neuron i0 + h*32 + lane.
// State path bitwise-locked: ordered mask decode -> strictly increasing-j
// sequential __fadd_rn chain per neuron; v' = fma(BETA,v,R)+I-s.
__global__ void __launch_bounds__(THREADS, 1) lif_kernel(float* __restrict__ out,
                                                         const float* __restrict__ Wout)
{
    extern __shared__ float smem[];
    float*          Ws     = smem;                               // [NN][NT], 128KB
    unsigned short* s_list = (unsigned short*)(smem + NN * NT);  // [32][NN], 32KB

    const int blk  = blockIdx.x;
    const int bg   = blk >> 3;          // 0..15
    const int nt   = blk & 7;           // 0..7
    const int b0   = bg * BT;
    const int i0   = nt * NT;
    const int tid  = threadIdx.x;
    const int warp = tid >> 5, lane = tid & 31;
    const int w2   = warp >> 1;         // row index within group (0..15)
    const int h    = warp & 1;          // half-tile (0..1)
    const int b    = b0 + w2;           // this warp's batch row
    // one warp per row per group finalizes: block nt == row&7, half h == bit3 of row
    const bool finalizer = ((w2 & 7) == nt) && (h == ((w2 >> 3) & 1));
    GroupBar* bar = &g_bar[bg];

    // Load W slice (coalesced; layout Ws[j][il], il = 0..63)
    {
        const int jl = tid >> 6, il = tid & 63;
        for (int j = jl; j < NN; j += 16)
            Ws[j * NT + il] = g_WT[j * NN + i0 + il];
    }
    __syncthreads();

    float wo[AA];
    #pragma unroll
    for (int a = 0; a < AA; a++) wo[a] = Wout[a * NN + i0 + h * 32 + lane];

    const float*    Ibase = g_I + (size_t)b * TT * NN + i0 + h * 32 + lane;
    const float*    wsl   = Ws + h * 32 + lane;
    unsigned short* lst   = s_list + warp * NN;      // each warp: own list copy

    float v = 0.f;
    bool  sp = false;
    float In = __ldg(Ibase);   // I(0)

    // masks(par0) zeroed by fused prep (kernel ordering); no initial barrier needed.
    for (int t = 0; t < TT; t++) {
        const int par = t & 1;

        // Prefetch I(t+1): off the critical path by a full step
        const float Ic = In;
        {
            int tn = (t + 1 < TT) ? t + 1 : t;
            In = __ldg(Ibase + (size_t)tn * NN);
        }

        // Read my row's 16 mask words (one coalesced 64B L2 load) — issue early
        unsigned mw = (lane < 16) ? __ldcg(&g_mask[par][b][lane]) : 0u;

        // Finalize out(t-1) for my own row (output path: tolerance-checked)
        if (t > 0 && finalizer) {
            const float* P = &g_part[par ^ 1][b][0][0];   // 128 contiguous floats
            float s = __ldcg(P + lane) + __ldcg(P + 32 + lane)
                    + __ldcg(P + 64 + lane) + __ldcg(P + 96 + lane);
            s += __shfl_xor_sync(0xffffffffu, s, 8);
            s += __shfl_xor_sync(0xffffffffu, s, 16);
            if (lane < AA)
                out[((size_t)b * TT + (t - 1)) * AA + lane] = tanhf(s);
        }

        // Decode masks to ordered spike list in smem (increasing j)
        int nsp = 0;
        #pragma unroll
        for (int w16 = 0; w16 < 16; w16++) {
            unsigned m = __shfl_sync(0xffffffffu, mw, w16);
            if ((m >> lane) & 1u)
                lst[nsp + __popc(m & ((1u << lane) - 1u))] = (unsigned short)(w16 * 32 + lane);
            nsp += __popc(m);
        }
        __syncwarp();

        // Sparse gather: one LDS.32 + one __fadd_rn per spike (strictly increasing j)
        float R = 0.f;
        int l = 0;
        for (; l + 4 <= nsp; l += 4) {
            ushort4 j4 = *reinterpret_cast<const ushort4*>(lst + l);
            float f0 = wsl[(int)j4.x * NT];
            float f1 = wsl[(int)j4.y * NT];
            float f2 = wsl[(int)j4.z * NT];
            float f3 = wsl[(int)j4.w * NT];
            R = __fadd_rn(R, f0); R = __fadd_rn(R, f1);
            R = __fadd_rn(R, f2); R = __fadd_rn(R, f3);
        }
        for (; l < nsp; l++)
            R = __fadd_rn(R, wsl[(int)lst[l] * NT]);

        // v' = (fma(BETA,v,R) + I) - V_TH*s   (locked ordering)
        float acc = __fmaf_rn(BETA, v, R);
        acc = __fadd_rn(acc, Ic);
        if (sp) acc = __fadd_rn(acc, -V_TH);
        v = acc; sp = v > V_TH;

        // Publish mask(t+1): my half-tile is exactly one word (natural order)
        unsigned m0 = __ballot_sync(0xffffffffu, sp);
        if (lane == 0) g_mask[par ^ 1][b][nt * 2 + h] = m0;

        // Output partials: 23-shuffle reduce of p[a] = v*wo[a] over 32 lanes
        {
            float p[AA];
            #pragma unroll
            for (int a = 0; a < AA; a++) {
                p[a] = v * wo[a];
                p[a] += __shfl_xor_sync(0xffffffffu, p[a], 16);
                p[a] += __shfl_xor_sync(0xffffffffu, p[a], 8);
            }
            const int hi4 = lane & 4, hi2 = lane & 2, hi1 = lane & 1;
            float q[4];
            #pragma unroll
            for (int a = 0; a < 4; a++) {
                int own = hi4 ? a + 4 : a;
                int snd = hi4 ? a : a + 4;
                q[a] = p[own] + __shfl_xor_sync(0xffffffffu, p[snd], 4);
            }
            float r2[2];
            #pragma unroll
            for (int a = 0; a < 2; a++) {
                int own = hi2 ? a + 2 : a;
                int snd = hi2 ? a : a + 2;
                r2[a] = q[own] + __shfl_xor_sync(0xffffffffu, q[snd], 2);
            }
            float rf = (hi1 ? r2[1] : r2[0])
                     + __shfl_xor_sync(0xffffffffu, hi1 ? r2[0] : r2[1], 1);
            if (lane < AA) g_part[par][b][nt * 2 + h][lane] = rf;
        }

        group_barrier(bar, (unsigned)(t + 1));
    }

    // Finalize out(TT-1) (last barrier made partials(TT-1) visible group-wide)
    if (finalizer) {
        const float* P = &g_part[(TT - 1) & 1][b][0][0];
        float s = __ldcg(P + lane) + __ldcg(P + 32 + lane)
                + __ldcg(P + 64 + lane) + __ldcg(P + 96 + lane);
        s += __shfl_xor_sync(0xffffffffu, s, 8);
        s += __shfl_xor_sync(0xffffffffu, s, 16);
        if (lane < AA)
            out[((size_t)b * TT + (TT - 1)) * AA + lane] = tanhf(s);
    }
}

extern "C" void kernel_launch(void* const* d_in, const int* in_sizes, int n_in,
                              void* d_out, int out_size)
{
    const float* X    = (const float*)d_in[0];  // [B,T,OBS]
    const float* Wrec = (const float*)d_in[1];  // [N,N]
    const float* Win  = (const float*)d_in[2];  // [N,OBS]
    const float* Wout = (const float*)d_in[3];  // [A,N]
    float*       out  = (float*)d_out;          // [B,T,A]

    const int smem_bytes = NN * NT * 4 + 32 * NN * 2;   // 128KB W + 32KB lists
    static bool attr_done = false;
    if (!attr_done) {
        cudaFuncSetAttribute(lif_kernel, cudaFuncAttributeMaxDynamicSharedMemorySize, smem_bytes);
        attr_done = true;
    }

    // 2 launches per call -> ncu -s 5 -c 1 lands on the lif kernel
    dim3 g((BB * TT) / 128, 9);   // y<8: gemm tiles; y==8: prep plane
    fused_prep_ingemm<<<g, 256>>>(X, Win, Wrec);
    lif_kernel<<<GRID, THREADS, smem_bytes>>>(out, Wout);
}

// round 16
// speedup vs baseline: 1.2138x; 1.2138x over previous
#include <cuda_runtime.h>
#include <cstdint>
#include <cmath>

#define BB   256
#define TT   1024
#define OBS  64
#define NN   512
#define AA   8
#define BETA 0.9f
#define V_TH 1.0f

#define NT      64                 // neurons per block
#define NNT     (NN / NT)          // 8 tile-blocks per group
#define NBG     32                 // 32 groups of 8 batch rows
#define GRID    128                // 16 bg-pairs x 8 tiles, all co-resident (1/SM)
#define THREADS 512                // 16 warps: warps 0-7 -> group A, 8-15 -> group B

struct __align__(128) GroupBar { unsigned count; unsigned flag; unsigned pad[30]; };

// Scratch: __device__ globals (runtime allocation is forbidden)
__device__ float    g_WT[NN * NN];               // W_T[j][i] = W_rec[i][j]
__device__ float    g_I[(size_t)BB * TT * NN];   // x @ W_in^T, precomputed
__device__ unsigned g_mask[2][BB][NN / 32];      // spike bitmasks, parity-buffered
__device__ float    g_part[2][BB][NNT][AA];      // output partials, parity-buffered
__device__ GroupBar g_bar[NBG];                  // per-group barrier lines

// ---------- fused prep + input GEMM ----------
// blockIdx.y < 8 : GEMM tile  g_I[r,i] = sum_k X[r,k]*Win[i,k]  (bitwise-load-bearing)
// blockIdx.y == 8: prep plane (W transpose, mask(0) zero, barrier reset)
__global__ void __launch_bounds__(256, 2) fused_prep_ingemm(const float* __restrict__ X,
                                                            const float* __restrict__ Win,
                                                            const float* __restrict__ Wrec)
{
    if (blockIdx.y == 8) {
        int idx = blockIdx.x * 256 + threadIdx.x;
        if (idx < NN * NN) {
            int i = idx >> 9, j = idx & (NN - 1);
            g_WT[j * NN + i] = Wrec[idx];
        }
        if (idx < BB * (NN / 32)) ((unsigned*)g_mask)[idx] = 0u;   // g_mask[0] zeroed
        if (idx < NBG) { g_bar[idx].count = 0u; g_bar[idx].flag = 0u; }
        return;
    }

    __shared__ float As[128][OBS];
    __shared__ float Bs[OBS][64];
    const int row0 = blockIdx.x * 128;
    const int col0 = blockIdx.y * 64;
    const int tid  = threadIdx.x;

    #pragma unroll
    for (int l = tid; l < 128 * 16; l += 256) {
        int r = l >> 4, kq = l & 15;
        float4 v = reinterpret_cast<const float4*>(X + (size_t)(row0 + r) * OBS)[kq];
        *reinterpret_cast<float4*>(&As[r][kq * 4]) = v;
    }
    #pragma unroll
    for (int l = tid; l < 64 * 16; l += 256) {
        int i = l & 63, kq = l >> 6;
        float4 v = reinterpret_cast<const float4*>(Win + (size_t)(col0 + i) * OBS)[kq];
        Bs[kq * 4 + 0][i] = v.x;
        Bs[kq * 4 + 1][i] = v.y;
        Bs[kq * 4 + 2][i] = v.z;
        Bs[kq * 4 + 3][i] = v.w;
    }
    __syncthreads();

    const int tx = tid & 15, ty = tid >> 4;
    float acc[8][4];
    #pragma unroll
    for (int u = 0; u < 8; u++)
        #pragma unroll
        for (int c = 0; c < 4; c++) acc[u][c] = 0.f;

    #pragma unroll 8
    for (int k = 0; k < OBS; k++) {
        float4 b4 = *reinterpret_cast<const float4*>(&Bs[k][tx * 4]);
        #pragma unroll
        for (int u = 0; u < 8; u++) {
            float a = As[ty * 8 + u][k];
            acc[u][0] = __fmaf_rn(a, b4.x, acc[u][0]);
            acc[u][1] = __fmaf_rn(a, b4.y, acc[u][1]);
            acc[u][2] = __fmaf_rn(a, b4.z, acc[u][2]);
            acc[u][3] = __fmaf_rn(a, b4.w, acc[u][3]);
        }
    }
    #pragma unroll
    for (int u = 0; u < 8; u++) {
        size_t r = (size_t)(row0 + ty * 8 + u);
        float4 st = make_float4(acc[u][0], acc[u][1], acc[u][2], acc[u][3]);
        *reinterpret_cast<float4*>(&g_I[r * NN + col0 + tx * 4]) = st;
    }
}

// ---------- half-block group barrier: named bar.sync(256) + 8-arrival flag ----------
// Each 256-thread half syncs only with its own group's 8 tile-blocks.
// While one half spins, the other half's warps keep issuing (latency overlap).
__device__ __forceinline__ void group_barrier_half(GroupBar* bar, unsigned target,
                                                   int h, int tid)
{
    asm volatile("bar.sync %0, %1;" :: "r"(h + 1), "r"(256) : "memory");
    if (tid == h * 256) {
        unsigned prev, one = 1u;
        asm volatile("atom.release.gpu.add.u32 %0, [%1], %2;"
                     : "=r"(prev) : "l"(&bar->count), "r"(one) : "memory");
        if (prev == target * NNT - 1u) {
            asm volatile("st.release.gpu.u32 [%0], %1;"
                         :: "l"(&bar->flag), "r"(target) : "memory");
        } else {
            unsigned f;
            do {
                asm volatile("ld.acquire.gpu.u32 %0, [%1];"
                             : "=r"(f) : "l"(&bar->flag) : "memory");
            } while (f < target);
        }
    }
    asm volatile("bar.sync %0, %1;" :: "r"(h + 1), "r"(256) : "memory");
}

// ---------- persistent LIF: W slice in SMEM, two independent 8-row groups/block ----------
// block = (bg-pair bg2) x (neuron tile nt); warp w -> row bg2*16 + w; half h = w>>3
// belongs to group 2*bg2+h. Lane owns neurons i0+lane and i0+32+lane.
// State path bitwise-identical to the 8006us kernel: ordered mask decode ->
// strictly increasing-j sequential __fadd_rn; v' = fma(BETA,v,R)+I-s.
__global__ void __launch_bounds__(THREADS, 1) lif_kernel(float* __restrict__ out,
                                                         const float* __restrict__ Wout)
{
    extern __shared__ float smem[];
    float*          Ws     = smem;                               // [NN][NT], 128KB
    unsigned short* s_list = (unsigned short*)(smem + NN * NT);  // [16][NN], 16KB

    const int blk  = blockIdx.x;
    const int bg2  = blk >> 3;         // 0..15 (pair of groups)
    const int nt   = blk & 7;          // 0..7
    const int b0   = bg2 * 16;
    const int i0   = nt * NT;
    const int tid  = threadIdx.x;
    const int warp = tid >> 5, lane = tid & 31;
    const int h    = warp >> 3;        // half: 0 or 1 -> group 2*bg2+h
    const int b    = b0 + warp;        // this warp's batch row (same map as 8006us kernel)
    const bool finalizer = ((warp & 7) == nt);   // 2 warps/block finalize own rows
    GroupBar* bar = &g_bar[bg2 * 2 + h];

    // Load W slice (coalesced; both halves cooperate — done once)
    {
        const int jl = tid >> 6, il = tid & 63;
        for (int j = jl; j < NN; j += 8)
            Ws[j * NT + il] = g_WT[j * NN + i0 + il];
    }
    __syncthreads();

    float wo0[AA], wo1[AA];
    #pragma unroll
    for (int a = 0; a < AA; a++) {
        wo0[a] = Wout[a * NN + i0 + lane];
        wo1[a] = Wout[a * NN + i0 + 32 + lane];
    }

    const float*    Ibase = g_I + (size_t)b * TT * NN + i0 + lane;
    const float*    wsl   = Ws + lane;
    unsigned short* lst   = s_list + warp * NN;

    float v0 = 0.f, v1 = 0.f;
    bool  sp0 = false, sp1 = false;
    float In0 = __ldg(Ibase), In1 = __ldg(Ibase + 32);   // I(0)

    // masks(par0) zeroed by fused prep (kernel ordering); no initial barrier needed.
    for (int t = 0; t < TT; t++) {
        const int par = t & 1;

        // Prefetch I(t+1): off the critical path by a full step
        const float Ic0 = In0, Ic1 = In1;
        {
            int tn = (t + 1 < TT) ? t + 1 : t;
            In0 = __ldg(Ibase + (size_t)tn * NN);
            In1 = __ldg(Ibase + (size_t)tn * NN + 32);
        }

        // Read my row's 16 mask words (one coalesced 64B L2 load) — issue early
        unsigned mw = (lane < 16) ? __ldcg(&g_mask[par][b][lane]) : 0u;

        // Finalize out(t-1) for my own row (output path: tolerance-checked)
        if (t > 0 && finalizer) {
            const float* P = &g_part[par ^ 1][b][0][0];   // 64 contiguous floats
            float s = __ldcg(P + lane) + __ldcg(P + 32 + lane);
            s += __shfl_xor_sync(0xffffffffu, s, 8);
            s += __shfl_xor_sync(0xffffffffu, s, 16);
            if (lane < AA)
                out[((size_t)b * TT + (t - 1)) * AA + lane] = tanhf(s);
        }

        // Decode masks to ordered spike list in smem (increasing j)
        int nsp = 0;
        #pragma unroll
        for (int w16 = 0; w16 < 16; w16++) {
            unsigned m = __shfl_sync(0xffffffffu, mw, w16);
            if ((m >> lane) & 1u)
                lst[nsp + __popc(m & ((1u << lane) - 1u))] = (unsigned short)(w16 * 32 + lane);
            nsp += __popc(m);
        }
        __syncwarp();

        // Sparse gather from SMEM: strict sequential __fadd_rn, increasing j.
        // One ushort4 broadcast LDS.64 per 4 spikes; 8 data-LDS in flight.
        float R0 = 0.f, R1 = 0.f;
        int l = 0;
        for (; l + 4 <= nsp; l += 4) {
            ushort4 j4 = *reinterpret_cast<const ushort4*>(lst + l);
            float a0 = wsl[(int)j4.x * NT], c0 = wsl[(int)j4.x * NT + 32];
            float a1 = wsl[(int)j4.y * NT], c1 = wsl[(int)j4.y * NT + 32];
            float a2 = wsl[(int)j4.z * NT], c2 = wsl[(int)j4.z * NT + 32];
            float a3 = wsl[(int)j4.w * NT], c3 = wsl[(int)j4.w * NT + 32];
            R0 = __fadd_rn(R0, a0); R1 = __fadd_rn(R1, c0);
            R0 = __fadd_rn(R0, a1); R1 = __fadd_rn(R1, c1);
            R0 = __fadd_rn(R0, a2); R1 = __fadd_rn(R1, c2);
            R0 = __fadd_rn(R0, a3); R1 = __fadd_rn(R1, c3);
        }
        for (; l < nsp; l++) {
            int j = lst[l];
            R0 = __fadd_rn(R0, wsl[j * NT]);
            R1 = __fadd_rn(R1, wsl[j * NT + 32]);
        }

        // v' = (fma(BETA,v,R) + I) - V_TH*s   (locked ordering)
        float acc0 = __fmaf_rn(BETA, v0, R0);
        acc0 = __fadd_rn(acc0, Ic0);
        if (sp0) acc0 = __fadd_rn(acc0, -V_TH);
        v0 = acc0; sp0 = v0 > V_TH;

        float acc1 = __fmaf_rn(BETA, v1, R1);
        acc1 = __fadd_rn(acc1, Ic1);
        if (sp1) acc1 = __fadd_rn(acc1, -V_TH);
        v1 = acc1; sp1 = v1 > V_TH;

        // Publish masks(t+1) + output partials(t) for my tile
        unsigned m0 = __ballot_sync(0xffffffffu, sp0);
        unsigned m1 = __ballot_sync(0xffffffffu, sp1);

        float p[AA];
        #pragma unroll
        for (int a = 0; a < AA; a++) {
            p[a] = v0 * wo0[a] + v1 * wo1[a];
            #pragma unroll
            for (int off = 16; off > 0; off >>= 1)
                p[a] += __shfl_down_sync(0xffffffffu, p[a], off);
        }
        if (lane == 0) {
            g_mask[par ^ 1][b][nt * 2 + 0] = m0;
            g_mask[par ^ 1][b][nt * 2 + 1] = m1;
            #pragma unroll
            for (int a = 0; a < AA; a++) g_part[par][b][nt][a] = p[a];
        }

        // Half-block barrier: only my group's 8 tile-blocks; other half keeps issuing
        group_barrier_half(bar, (unsigned)(t + 1), h, tid);
    }

    // Finalize out(TT-1) (last barrier made partials(TT-1) visible group-wide)
    if (finalizer) {
        const float* P = &g_part[(TT - 1) & 1][b][0][0];
        float s = __ldcg(P + lane) + __ldcg(P + 32 + lane);
        s += __shfl_xor_sync(0xffffffffu, s, 8);
        s += __shfl_xor_sync(0xffffffffu, s, 16);
        if (lane < AA)
            out[((size_t)b * TT + (TT - 1)) * AA + lane] = tanhf(s);
    }
}

extern "C" void kernel_launch(void* const* d_in, const int* in_sizes, int n_in,
                              void* d_out, int out_size)
{
    const float* X    = (const float*)d_in[0];  // [B,T,OBS]
    const float* Wrec = (const float*)d_in[1];  // [N,N]
    const float* Win  = (const float*)d_in[2];  // [N,OBS]
    const float* Wout = (const float*)d_in[3];  // [A,N]
    float*       out  = (float*)d_out;          // [B,T,A]

    const int smem_bytes = NN * NT * 4 + 16 * NN * 2;   // 128KB W + 16KB lists
    static bool attr_done = false;
    if (!attr_done) {
        cudaFuncSetAttribute(lif_kernel, cudaFuncAttributeMaxDynamicSharedMemorySize, smem_bytes);
        attr_done = true;
    }

    // 2 launches per call -> ncu -s 5 -c 1 lands on the lif kernel
    dim3 g((BB * TT) / 128, 9);   // y<8: gemm tiles; y==8: prep plane
    fused_prep_ingemm<<<g, 256>>>(X, Win, Wrec);
    lif_kernel<<<GRID, THREADS, smem_bytes>>>(out, Wout);
}